// round 7
// baseline (speedup 1.0000x reference)
#include <cuda_runtime.h>

#define N_NODES 100000
#define N_EDGES 1000000
#define IN_DIM  128
#define HID     64
#define NG      2048

// ---------------- scratch (static __device__, no allocation) ----------------
__device__ int   g_eor = 0, g_bor = 0;  // dtype detection (monotone: 0 => int64)
__device__ int   g_cnt[N_NODES];        // in-degree counter (self-cleaning, starts 0)
__device__ int   g_deg[N_NODES];        // edge count excluding self loop
__device__ float g_dinv[N_NODES];
__device__ int   g_col[N_EDGES];
__device__ int   g_off[N_NODES];
__device__ int   g_cur[N_NODES];
__device__ int   g_csr[N_EDGES];
__device__ int   g_alloc;
__device__ __align__(16) float g_bufA[N_NODES * HID];   // gemm1 out h1; later B2
__device__ __align__(16) float g_bufB[N_NODES * HID];   // u2 = dinv*(B1@W2)
__device__ __align__(16) float g_pooled[NG * HID];

__device__ __forceinline__ int clampi(int v, int lo, int hi) {
    return v < lo ? lo : (v > hi ? hi : v);
}

// ---------------- tf32 helpers ----------------
__device__ __forceinline__ unsigned f2tf(float x) {
    unsigned r;
    asm("cvt.rna.tf32.f32 %0, %1;" : "=r"(r) : "f"(x));
    return r;
}

__device__ __forceinline__ void mma_tf32(float* d, const unsigned* a, const unsigned* b) {
    asm volatile(
        "mma.sync.aligned.m16n8k8.row.col.f32.tf32.tf32.f32 "
        "{%0,%1,%2,%3},{%4,%5,%6,%7},{%8,%9},{%0,%1,%2,%3};\n"
        : "+f"(d[0]), "+f"(d[1]), "+f"(d[2]), "+f"(d[3])
        : "r"(a[0]), "r"(a[1]), "r"(a[2]), "r"(a[3]), "r"(b[0]), "r"(b[1]));
}

// ------- init: pooled=0, g_alloc=0, dtype detection -------
__global__ void k_init(const int* __restrict__ ew, const int* __restrict__ bw) {
    int i = blockIdx.x * blockDim.x + threadIdx.x;
    if (i < NG * HID) g_pooled[i] = 0.f;
    if (i == 0) g_alloc = 0;
    if (i < 1024) {
        if (ew[2 * i + 1] != 0) atomicOr(&g_eor, 1);
        if (bw[2 * i + 1] != 0) atomicOr(&g_bor, 1);
    }
}

// ---------------- edge pass: count in-degree, 2 edges per thread ----------------
__global__ void k_edges(const int* __restrict__ ew) {
    int e2 = blockIdx.x * blockDim.x + threadIdx.x;
    if (e2 * 2 >= N_EDGES) return;
    int c0, c1;
    if (g_eor == 0) {
        int4 v = reinterpret_cast<const int4*>(ew)[(N_EDGES >> 1) + e2]; // dst int64 pairs
        c0 = v.x; c1 = v.z;
    } else {
        int2 v = reinterpret_cast<const int2*>(ew + N_EDGES)[e2];
        c0 = v.x; c1 = v.y;
    }
    c0 = clampi(c0, 0, N_NODES - 1);
    c1 = clampi(c1, 0, N_NODES - 1);
    int2 cc; cc.x = c0; cc.y = c1;
    reinterpret_cast<int2*>(g_col)[e2] = cc;
    atomicAdd(&g_cnt[c0], 1);
    atomicAdd(&g_cnt[c1], 1);
}

// ------- per node: dinv, atomic range allocation; self-clean g_cnt -------
__global__ void k_alloc() {
    int i = blockIdx.x * blockDim.x + threadIdx.x;
    if (i >= N_NODES) return;
    int cnt = g_cnt[i];
    g_cnt[i] = 0;                          // reset for next run
    g_deg[i] = cnt;
    g_dinv[i] = rsqrtf((float)(cnt + 1));  // +1 self loop
    int o = atomicAdd(&g_alloc, cnt);
    g_off[i] = o;
    g_cur[i] = o;
}

// ---------------- fill CSR: 2 edges per thread ----------------
__global__ void k_fill(const int* __restrict__ ew) {
    int e2 = blockIdx.x * blockDim.x + threadIdx.x;
    if (e2 * 2 >= N_EDGES) return;
    int r0, r1;
    if (g_eor == 0) {
        int4 v = reinterpret_cast<const int4*>(ew)[e2];   // src int64 pairs
        r0 = v.x; r1 = v.z;
    } else {
        int2 v = reinterpret_cast<const int2*>(ew)[e2];
        r0 = v.x; r1 = v.y;
    }
    r0 = clampi(r0, 0, N_NODES - 1);
    r1 = clampi(r1, 0, N_NODES - 1);
    int2 cc = reinterpret_cast<const int2*>(g_col)[e2];
    int s0 = atomicAdd(&g_cur[cc.x], 1);
    if (s0 >= 0 && s0 < N_EDGES) g_csr[s0] = r0;
    int s1 = atomicAdd(&g_cur[cc.y], 1);
    if (s1 >= 0 && s1 < N_EDGES) g_csr[s1] = r1;
}

// ---------------- GEMM1: 3xTF32 MMA, g_bufA = X @ W1 ----------------
// Block 128 threads (4 warps), tile 128x64, K staged in 32-chunks.
__global__ __launch_bounds__(128) void k_gemm1(const float* __restrict__ X,
                                               const float* __restrict__ W) {
    __shared__ float abuf[4096];   // [k8(4)][m16(8)][lane(32)][reg(4)]
    __shared__ float bbuf[2048];   // [k8(4)][na(8)][lane(32)][reg(2)]

    int tid  = threadIdx.x;
    int lane = tid & 31;
    int warp = tid >> 5;
    int row0 = blockIdx.x * 128;

    float acc[2][8][4];
#pragma unroll
    for (int m = 0; m < 2; m++)
#pragma unroll
        for (int na = 0; na < 8; na++)
#pragma unroll
            for (int q = 0; q < 4; q++) acc[m][na][q] = 0.f;

    for (int ko = 0; ko < IN_DIM; ko += 32) {
        __syncthreads();
#pragma unroll
        for (int it = 0; it < 8; it++) {
            int f4 = it * 128 + tid;
            int r  = f4 >> 3;
            int c4 = (f4 & 7) * 4;
            int gr = row0 + r;
            float4 v = make_float4(0.f, 0.f, 0.f, 0.f);
            if (gr < N_NODES)
                v = *reinterpret_cast<const float4*>(X + gr * IN_DIM + ko + c4);
            int rr  = r & 15;
            int m16 = r >> 4;
            int k8  = c4 >> 3;
            int kkb = c4 & 7;
            float vv[4] = {v.x, v.y, v.z, v.w};
#pragma unroll
            for (int j = 0; j < 4; j++) {
                int kk  = kkb + j;
                int reg = ((rr >= 8) ? 1 : 0) + ((kk >= 4) ? 2 : 0);
                int t   = (rr & 7) * 4 + (kk & 3);
                abuf[((k8 * 8 + m16) * 32 + t) * 4 + reg] = vv[j];
            }
        }
#pragma unroll
        for (int it = 0; it < 4; it++) {
            int f4 = it * 128 + tid;
            int r  = f4 >> 4;
            int c4 = (f4 & 15) * 4;
            float4 w = *reinterpret_cast<const float4*>(W + (ko + r) * 64 + c4);
            int kk = r & 7;
            int k8 = r >> 3;
            float wv[4] = {w.x, w.y, w.z, w.w};
#pragma unroll
            for (int j = 0; j < 4; j++) {
                int n   = c4 + j;
                int na  = n >> 3;
                int nn  = n & 7;
                int reg = (kk >= 4) ? 1 : 0;
                int t   = nn * 4 + (kk & 3);
                bbuf[((k8 * 8 + na) * 32 + t) * 2 + reg] = wv[j];
            }
        }
        __syncthreads();

#pragma unroll
        for (int k8 = 0; k8 < 4; k8++) {
            unsigned a_hi[2][4], a_lo[2][4];
#pragma unroll
            for (int m = 0; m < 2; m++) {
                float4 ar = *reinterpret_cast<const float4*>(
                    abuf + ((k8 * 8 + warp * 2 + m) * 32 + lane) * 4);
                float av[4] = {ar.x, ar.y, ar.z, ar.w};
#pragma unroll
                for (int q = 0; q < 4; q++) {
                    unsigned h = f2tf(av[q]);
                    a_hi[m][q] = h;
                    a_lo[m][q] = f2tf(av[q] - __uint_as_float(h));
                }
            }
            unsigned b_hi[8][2], b_lo[8][2];
#pragma unroll
            for (int na = 0; na < 8; na++) {
                float2 br = *reinterpret_cast<const float2*>(
                    bbuf + ((k8 * 8 + na) * 32 + lane) * 2);
                float bv[2] = {br.x, br.y};
#pragma unroll
                for (int q = 0; q < 2; q++) {
                    unsigned h = f2tf(bv[q]);
                    b_hi[na][q] = h;
                    b_lo[na][q] = f2tf(bv[q] - __uint_as_float(h));
                }
            }
#pragma unroll
            for (int na = 0; na < 8; na++) {
#pragma unroll
                for (int m = 0; m < 2; m++) {
                    mma_tf32(acc[m][na], a_hi[m], b_hi[na]);
                    mma_tf32(acc[m][na], a_hi[m], b_lo[na]);
                    mma_tf32(acc[m][na], a_lo[m], b_hi[na]);
                }
            }
        }
    }

    int rbase = row0 + warp * 32 + (lane >> 2);
    int cbase = (lane & 3) * 2;
#pragma unroll
    for (int m = 0; m < 2; m++) {
        int r_lo = rbase + m * 16;
        int r_hi = r_lo + 8;
#pragma unroll
        for (int na = 0; na < 8; na++) {
            int c = na * 8 + cbase;
            if (r_lo < N_NODES) {
                float2 v; v.x = acc[m][na][0]; v.y = acc[m][na][1];
                *reinterpret_cast<float2*>(g_bufA + r_lo * 64 + c) = v;
            }
            if (r_hi < N_NODES) {
                float2 v; v.x = acc[m][na][2]; v.y = acc[m][na][3];
                *reinterpret_cast<float2*>(g_bufA + r_hi * 64 + c) = v;
            }
        }
    }
}

// ---- fused: agg1(+relu+b1) into smem fragments, then GEMM2, epilogue *dinv ----
// Block 128 threads; each warp aggregates 32 contiguous nodes; K=64 MMA from smem.
// Dynamic smem: abuf [k8(8)][m16(8)][lane(32)][reg(4)] = 32KB, bbuf [k8(8)][na(8)][lane(32)][reg(2)] = 16KB.
__global__ __launch_bounds__(128) void k_aggGemm2(const float* __restrict__ b1,
                                                  const float* __restrict__ W2) {
    extern __shared__ float smem[];
    float* abuf = smem;            // 8192 floats
    float* bbuf = smem + 8192;     // 4096 floats

    int tid  = threadIdx.x;
    int lane = tid & 31;
    int warp = tid >> 5;
    int row0 = blockIdx.x * 128;

    // ---- stage W2 (64x64) into fragment order ----
#pragma unroll
    for (int it = 0; it < 8; it++) {
        int f4 = it * 128 + tid;          // 0..1023
        int r  = f4 >> 4;                 // k: 0..63
        int c4 = (f4 & 15) * 4;           // n
        float4 w = *reinterpret_cast<const float4*>(W2 + r * 64 + c4);
        int kk = r & 7;
        int k8 = r >> 3;                  // 0..7
        float wv[4] = {w.x, w.y, w.z, w.w};
#pragma unroll
        for (int j = 0; j < 4; j++) {
            int n   = c4 + j;
            int na  = n >> 3;
            int nn  = n & 7;
            int reg = (kk >= 4) ? 1 : 0;
            int t   = nn * 4 + (kk & 3);
            bbuf[((k8 * 8 + na) * 32 + t) * 2 + reg] = wv[j];
        }
    }

    // ---- aggregate 32 nodes per warp; write relu rows into abuf fragments ----
    float bx = b1[2 * lane];
    float by = b1[2 * lane + 1];
    for (int j = 0; j < 32; j++) {
        int r = warp * 32 + j;            // local row 0..127
        int i = row0 + r;
        float ox = 0.f, oy = 0.f;
        if (i < N_NODES) {
            float di = g_dinv[i];
            float2 hs = *reinterpret_cast<const float2*>(g_bufA + i * 64 + 2 * lane);
            float ax = di * hs.x;
            float ay = di * hs.y;
            int beg = g_off[i];
            int end = beg + g_deg[i];
            if (beg < 0) beg = 0;
            if (end > N_EDGES) end = N_EDGES;
            int e = beg;
            for (; e + 4 <= end; e += 4) {
                int s0 = g_csr[e], s1 = g_csr[e + 1], s2 = g_csr[e + 2], s3 = g_csr[e + 3];
                float w0 = g_dinv[s0], w1 = g_dinv[s1], w2 = g_dinv[s2], w3 = g_dinv[s3];
                float2 v0 = *reinterpret_cast<const float2*>(g_bufA + s0 * 64 + 2 * lane);
                float2 v1 = *reinterpret_cast<const float2*>(g_bufA + s1 * 64 + 2 * lane);
                float2 v2 = *reinterpret_cast<const float2*>(g_bufA + s2 * 64 + 2 * lane);
                float2 v3 = *reinterpret_cast<const float2*>(g_bufA + s3 * 64 + 2 * lane);
                ax += w0 * v0.x + w1 * v1.x + w2 * v2.x + w3 * v3.x;
                ay += w0 * v0.y + w1 * v1.y + w2 * v2.y + w3 * v3.y;
            }
            for (; e < end; e++) {
                int s = g_csr[e];
                float w = g_dinv[s];
                float2 v = *reinterpret_cast<const float2*>(g_bufA + s * 64 + 2 * lane);
                ax += w * v.x;
                ay += w * v.y;
            }
            ox = fmaxf(di * ax + bx, 0.f);
            oy = fmaxf(di * ay + by, 0.f);
        }
        // scatter {ox, oy} into abuf fragment order (A row r, cols 2*lane, 2*lane+1)
        int rr  = r & 15;
        int m16 = r >> 4;
        float vals[2] = {ox, oy};
#pragma unroll
        for (int q = 0; q < 2; q++) {
            int c   = 2 * lane + q;
            int k8  = c >> 3;
            int kk  = c & 7;
            int reg = ((rr >= 8) ? 1 : 0) + ((kk >= 4) ? 2 : 0);
            int t   = (rr & 7) * 4 + (kk & 3);
            abuf[((k8 * 8 + m16) * 32 + t) * 4 + reg] = vals[q];
        }
    }
    __syncthreads();

    // ---- K=64 MMA: 8 k8 steps ----
    float acc[2][8][4];
#pragma unroll
    for (int m = 0; m < 2; m++)
#pragma unroll
        for (int na = 0; na < 8; na++)
#pragma unroll
            for (int q = 0; q < 4; q++) acc[m][na][q] = 0.f;

#pragma unroll
    for (int k8 = 0; k8 < 8; k8++) {
        unsigned a_hi[2][4], a_lo[2][4];
#pragma unroll
        for (int m = 0; m < 2; m++) {
            float4 ar = *reinterpret_cast<const float4*>(
                abuf + ((k8 * 8 + warp * 2 + m) * 32 + lane) * 4);
            float av[4] = {ar.x, ar.y, ar.z, ar.w};
#pragma unroll
            for (int q = 0; q < 4; q++) {
                unsigned h = f2tf(av[q]);
                a_hi[m][q] = h;
                a_lo[m][q] = f2tf(av[q] - __uint_as_float(h));
            }
        }
        unsigned b_hi[8][2], b_lo[8][2];
#pragma unroll
        for (int na = 0; na < 8; na++) {
            float2 br = *reinterpret_cast<const float2*>(
                bbuf + ((k8 * 8 + na) * 32 + lane) * 2);
            float bv[2] = {br.x, br.y};
#pragma unroll
            for (int q = 0; q < 2; q++) {
                unsigned h = f2tf(bv[q]);
                b_hi[na][q] = h;
                b_lo[na][q] = f2tf(bv[q] - __uint_as_float(h));
            }
        }
#pragma unroll
        for (int na = 0; na < 8; na++) {
#pragma unroll
            for (int m = 0; m < 2; m++) {
                mma_tf32(acc[m][na], a_hi[m], b_hi[na]);
                mma_tf32(acc[m][na], a_hi[m], b_lo[na]);
                mma_tf32(acc[m][na], a_lo[m], b_hi[na]);
            }
        }
    }

    // ---- epilogue: u2 = dinv[row] * h2 -> g_bufB ----
    int rbase = row0 + warp * 32 + (lane >> 2);
    int cbase = (lane & 3) * 2;
#pragma unroll
    for (int m = 0; m < 2; m++) {
        int r_lo = rbase + m * 16;
        int r_hi = r_lo + 8;
        float d_lo = (r_lo < N_NODES) ? g_dinv[r_lo] : 0.f;
        float d_hi = (r_hi < N_NODES) ? g_dinv[r_hi] : 0.f;
#pragma unroll
        for (int na = 0; na < 8; na++) {
            int c = na * 8 + cbase;
            if (r_lo < N_NODES) {
                float2 v; v.x = d_lo * acc[m][na][0]; v.y = d_lo * acc[m][na][1];
                *reinterpret_cast<float2*>(g_bufB + r_lo * 64 + c) = v;
            }
            if (r_hi < N_NODES) {
                float2 v; v.x = d_hi * acc[m][na][2]; v.y = d_hi * acc[m][na][3];
                *reinterpret_cast<float2*>(g_bufB + r_hi * 64 + c) = v;
            }
        }
    }
}

// -------- agg2: B2 = relu(dinv[i] * (u2_i + sum u2_s) + b2), prescaled input --------
__global__ __launch_bounds__(256) void k_agg2(const float* __restrict__ bias) {
    int warp = (blockIdx.x * blockDim.x + threadIdx.x) >> 5;
    int lane = threadIdx.x & 31;
    if (warp >= N_NODES) return;
    int i = warp;

    float2 hs = *reinterpret_cast<const float2*>(g_bufB + i * 64 + 2 * lane);
    float ax = hs.x;
    float ay = hs.y;

    int beg = g_off[i];
    int end = beg + g_deg[i];
    if (beg < 0) beg = 0;
    if (end > N_EDGES) end = N_EDGES;
    int e = beg;
    for (; e + 4 <= end; e += 4) {
        int s0 = g_csr[e], s1 = g_csr[e + 1], s2 = g_csr[e + 2], s3 = g_csr[e + 3];
        float2 v0 = *reinterpret_cast<const float2*>(g_bufB + s0 * 64 + 2 * lane);
        float2 v1 = *reinterpret_cast<const float2*>(g_bufB + s1 * 64 + 2 * lane);
        float2 v2 = *reinterpret_cast<const float2*>(g_bufB + s2 * 64 + 2 * lane);
        float2 v3 = *reinterpret_cast<const float2*>(g_bufB + s3 * 64 + 2 * lane);
        ax += v0.x + v1.x + v2.x + v3.x;
        ay += v0.y + v1.y + v2.y + v3.y;
    }
    for (; e < end; e++) {
        int s = g_csr[e];
        float2 v = *reinterpret_cast<const float2*>(g_bufB + s * 64 + 2 * lane);
        ax += v.x;
        ay += v.y;
    }

    float di = g_dinv[i];
    float bx = bias[2 * lane];
    float by = bias[2 * lane + 1];
    float2 o;
    o.x = fmaxf(di * ax + bx, 0.f);
    o.y = fmaxf(di * ay + by, 0.f);
    *reinterpret_cast<float2*>(g_bufA + i * 64 + 2 * lane) = o;   // B2 -> bufA
}

// -------- fused score + segmented pooling (batch sorted); reads bufA --------
__global__ __launch_bounds__(256) void k_pool(const int* __restrict__ bw,
                                              const float* __restrict__ aw,
                                              const float* __restrict__ ab,
                                              const float* __restrict__ mw,
                                              const float* __restrict__ mb) {
    int warp = (blockIdx.x * blockDim.x + threadIdx.x) >> 5;
    int lane = threadIdx.x & 31;
    int n0 = warp * 32;
    if (n0 >= N_NODES) return;
    int n1 = n0 + 32;
    if (n1 > N_NODES) n1 = N_NODES;

    int b64 = (g_bor == 0);
    float awx = aw[2 * lane], awy = aw[2 * lane + 1];
    float mwx = mw[2 * lane], mwy = mw[2 * lane + 1];
    float abv = ab[0], mbv = mb[0];

    int cur = -1;
    float accx = 0.f, accy = 0.f;
    for (int n = n0; n < n1; n++) {
        float2 h = *reinterpret_cast<const float2*>(g_bufA + n * 64 + 2 * lane);
        float pa = h.x * awx + h.y * awy;
        float pm = h.x * mwx + h.y * mwy;
#pragma unroll
        for (int o = 16; o > 0; o >>= 1) {
            pa += __shfl_xor_sync(0xffffffffu, pa, o);
            pm += __shfl_xor_sync(0xffffffffu, pm, o);
        }
        float score = (pa + abv) * (1.f / (1.f + expf(-(pm + mbv))));
        int g = b64 ? reinterpret_cast<const int2*>(bw)[n].x : bw[n];
        g = clampi(g, 0, NG - 1);
        if (g != cur) {
            if (cur >= 0) {
                atomicAdd(&g_pooled[cur * 64 + 2 * lane], accx);
                atomicAdd(&g_pooled[cur * 64 + 2 * lane + 1], accy);
            }
            cur = g;
            accx = 0.f;
            accy = 0.f;
        }
        accx += score * h.x;
        accy += score * h.y;
    }
    if (cur >= 0) {
        atomicAdd(&g_pooled[cur * 64 + 2 * lane], accx);
        atomicAdd(&g_pooled[cur * 64 + 2 * lane + 1], accy);
    }
}

// -------- final: out[g] = pooled[g] . out_w + out_b --------
__global__ void k_final(const float* __restrict__ ow, const float* __restrict__ ob,
                        float* __restrict__ out) {
    int warp = (blockIdx.x * blockDim.x + threadIdx.x) >> 5;
    int lane = threadIdx.x & 31;
    if (warp >= NG) return;
    float2 p = *reinterpret_cast<const float2*>(g_pooled + warp * 64 + 2 * lane);
    float wx = ow[2 * lane], wy = ow[2 * lane + 1];
    float s = p.x * wx + p.y * wy;
#pragma unroll
    for (int o = 16; o > 0; o >>= 1) s += __shfl_xor_sync(0xffffffffu, s, o);
    if (lane == 0) out[warp] = s + ob[0];
}

// ---------------------------------------------------------------------------
extern "C" void kernel_launch(void* const* d_in, const int* in_sizes, int n_in,
                              void* d_out, int out_size) {
    const float* x     = (const float*)d_in[0];
    const int*   ew    = (const int*)d_in[1];    // int32 word view of edge_index
    const int*   bw    = (const int*)d_in[2];    // int32 word view of batch
    const float* W1    = (const float*)d_in[3];
    const float* b1    = (const float*)d_in[4];
    const float* W2    = (const float*)d_in[5];
    const float* b2    = (const float*)d_in[6];
    const float* aw    = (const float*)d_in[7];
    const float* ab    = (const float*)d_in[8];
    const float* mw    = (const float*)d_in[9];
    const float* mb    = (const float*)d_in[10];
    const float* ow    = (const float*)d_in[11];
    const float* ob    = (const float*)d_in[12];
    float* out = (float*)d_out;

    static int smem_set = 0;
    if (!smem_set) {
        cudaFuncSetAttribute(k_aggGemm2, cudaFuncAttributeMaxDynamicSharedMemorySize,
                             49152);
        smem_set = 1;
    }

    int gemm_grid = (N_NODES + 127) / 128;

    // Fork: GEMM1 runs concurrently with the graph build.
    cudaStream_t s2;
    cudaEvent_t evFork, evJoin;
    cudaStreamCreateWithFlags(&s2, cudaStreamNonBlocking);
    cudaEventCreateWithFlags(&evFork, cudaEventDisableTiming);
    cudaEventCreateWithFlags(&evJoin, cudaEventDisableTiming);

    cudaEventRecord(evFork, 0);
    cudaStreamWaitEvent(s2, evFork, 0);
    k_gemm1<<<gemm_grid, 128, 0, s2>>>(x, W1);
    cudaEventRecord(evJoin, s2);

    // Graph build on main stream.
    k_init<<<(NG * HID + 255) / 256, 256>>>(ew, bw);
    k_edges<<<(N_EDGES / 2 + 255) / 256, 256>>>(ew);
    k_alloc<<<(N_NODES + 255) / 256, 256>>>();
    k_fill<<<(N_EDGES / 2 + 255) / 256, 256>>>(ew);

    cudaStreamWaitEvent(0, evJoin, 0);

    k_aggGemm2<<<gemm_grid, 128, 49152>>>(b1, W2);
    k_agg2<<<(N_NODES * 32 + 255) / 256, 256>>>(b2);
    k_pool<<<(N_NODES + 255) / 256, 256>>>(bw, aw, ab, mw, mb);
    k_final<<<(NG * 32 + 255) / 256, 256>>>(ow, ob, out);
}